// round 1
// baseline (speedup 1.0000x reference)
#include <cuda_runtime.h>
#include <math.h>

#define Bc 8
#define Lc 1024
#define Dc 256
#define Hc 8
#define HDc 32
#define Mc (Bc*Lc)   // 8192

// Scratch (allocation-free: __device__ globals)
__device__ float g_k[Mc*Dc];
__device__ float g_v[Mc*Dc];
__device__ float g_q[Mc*Dc];
__device__ float g_sk[Mc*Dc];
__device__ float g_sv[Mc*Dc];
__device__ float g_y[Mc*Dc];

// ---------------------------------------------------------------------------
// GEMM: C[M,N] = A[M,K] @ W[K,N] + bias,  A cols [0,K0) from A0, [K0,K) from A1
// Tiles: 64x64x16, 256 threads, 4x4 register microtile.
// ---------------------------------------------------------------------------
__global__ __launch_bounds__(256)
void gemm_bias_kernel(const float* __restrict__ A0,
                      const float* __restrict__ A1,
                      int K0, int K,
                      const float* __restrict__ W,
                      const float* __restrict__ bias,
                      float* __restrict__ C, int N)
{
    __shared__ float As[16][64];
    __shared__ float Ws[16][64];
    const int tid = threadIdx.x;
    const int tx = tid % 16;
    const int ty = tid / 16;
    const int m0 = blockIdx.y * 64;
    const int n0 = blockIdx.x * 64;
    const int K1 = K - K0;

    float acc[4][4] = {};

    for (int k0 = 0; k0 < K; k0 += 16) {
        // A tile: 64 rows x 16 k
        #pragma unroll
        for (int i = 0; i < 4; i++) {
            int idx = tid + i * 256;      // 0..1023
            int mm = idx >> 4;            // 0..63
            int kk = idx & 15;
            int gk = k0 + kk;
            float val;
            if (gk < K0) val = A0[(m0 + mm) * K0 + gk];
            else         val = A1[(m0 + mm) * K1 + (gk - K0)];
            As[kk][mm] = val;
        }
        // W tile: 16 k x 64 n
        #pragma unroll
        for (int i = 0; i < 4; i++) {
            int idx = tid + i * 256;
            int kk = idx >> 6;            // 0..15
            int nn = idx & 63;
            Ws[kk][nn] = W[(k0 + kk) * N + n0 + nn];
        }
        __syncthreads();
        #pragma unroll
        for (int kk = 0; kk < 16; kk++) {
            float a[4], w[4];
            #pragma unroll
            for (int i = 0; i < 4; i++) a[i] = As[kk][ty * 4 + i];
            #pragma unroll
            for (int j = 0; j < 4; j++) w[j] = Ws[kk][tx * 4 + j];
            #pragma unroll
            for (int i = 0; i < 4; i++)
                #pragma unroll
                for (int j = 0; j < 4; j++)
                    acc[i][j] += a[i] * w[j];
        }
        __syncthreads();
    }

    #pragma unroll
    for (int i = 0; i < 4; i++) {
        int mm = m0 + ty * 4 + i;
        #pragma unroll
        for (int j = 0; j < 4; j++) {
            int nn = n0 + tx * 4 + j;
            C[mm * N + nn] = acc[i][j] + bias[nn];
        }
    }
}

// ---------------------------------------------------------------------------
// Attention: 1 thread = 1 query row. Online softmax over 128-key tiles in smem.
// Diagonal term (self_k / self_v) seeds the online state; j==l skipped in loop.
// Mask packed to bits per tile via ballot (coalesced global reads).
// ---------------------------------------------------------------------------
__global__ __launch_bounds__(128)
void attn_kernel(const float* __restrict__ q,
                 const float* __restrict__ k,
                 const float* __restrict__ v,
                 const float* __restrict__ sk,
                 const float* __restrict__ sv,
                 const int*   __restrict__ mask,
                 float* __restrict__ y)
{
    __shared__ float Ks[128][HDc];
    __shared__ float Vs[128][HDc];
    __shared__ unsigned Mbits[128][4];

    const int bh = blockIdx.y;
    const int b = bh / Hc, h = bh % Hc;
    const int l0 = blockIdx.x * 128;
    const int tid = threadIdx.x;
    const int lane = tid & 31;
    const int wid = tid >> 5;
    const int l = l0 + tid;
    const int row = (b * Lc + l) * Dc + h * HDc;
    const float scale = 0.17677669529663687f;   // 1/sqrt(32)
    const float NEG_INF = __int_as_float(0xff800000);

    float qreg[HDc];
    #pragma unroll
    for (int d = 0; d < HDc; d++) qreg[d] = q[row + d];

    // self (diagonal) score
    float sw = 0.f;
    #pragma unroll
    for (int d = 0; d < HDc; d++) sw += qreg[d] * sk[row + d];
    sw *= scale;

    float mrun = NEG_INF, sum = 0.f;
    float acc[HDc];
    #pragma unroll
    for (int d = 0; d < HDc; d++) acc[d] = 0.f;

    // seed online state with the diagonal term (value = self_v)
    if (mask[(b * Lc + l) * Lc + l] != 0) {
        mrun = sw; sum = 1.f;
        #pragma unroll
        for (int d = 0; d < HDc; d++) acc[d] = sv[row + d];
    }

    for (int j0 = 0; j0 < Lc; j0 += 128) {
        __syncthreads();
        // K/V tile load (coalesced: each warp covers consecutive floats)
        for (int idx = tid; idx < 128 * (HDc / 4); idx += 128) {
            int jj = idx / (HDc / 4);
            int dd = (idx % (HDc / 4)) * 4;
            int g = (b * Lc + j0 + jj) * Dc + h * HDc + dd;
            *(float4*)&Ks[jj][dd] = *(const float4*)&k[g];
            *(float4*)&Vs[jj][dd] = *(const float4*)&v[g];
        }
        // mask tile -> bitmask (coalesced rows, ballot-packed)
        for (int r = wid; r < 128; r += 4) {
            #pragma unroll
            for (int w = 0; w < 4; w++) {
                int gidx = (b * Lc + l0 + r) * Lc + j0 + w * 32 + lane;
                unsigned bits = __ballot_sync(0xffffffffu, mask[gidx] != 0);
                if (lane == 0) Mbits[r][w] = bits;
            }
        }
        __syncthreads();

        unsigned mb[4];
        #pragma unroll
        for (int w = 0; w < 4; w++) mb[w] = Mbits[tid][w];

        #pragma unroll
        for (int w = 0; w < 4; w++) {
            unsigned mw = mb[w];
            #pragma unroll 4
            for (int t = 0; t < 32; t++) {
                int jj = w * 32 + t;
                int j = j0 + jj;
                if (j == l) continue;                 // diagonal already seeded
                if (!((mw >> t) & 1u)) continue;      // masked out
                float s = 0.f;
                #pragma unroll
                for (int d = 0; d < HDc; d++) s += qreg[d] * Ks[jj][d];
                s *= scale;
                if (s > mrun) {
                    float corr = __expf(mrun - s);
                    sum *= corr;
                    #pragma unroll
                    for (int d = 0; d < HDc; d++) acc[d] *= corr;
                    mrun = s;
                }
                float p = __expf(s - mrun);
                sum += p;
                #pragma unroll
                for (int d = 0; d < HDc; d++) acc[d] += p * Vs[jj][d];
            }
        }
    }

    float inv = (sum > 0.f) ? (1.f / sum) : 0.f;
    #pragma unroll
    for (int d = 0; d < HDc; d++) y[row + d] = acc[d] * inv;
}

// ---------------------------------------------------------------------------
extern "C" void kernel_launch(void* const* d_in, const int* in_sizes, int n_in,
                              void* d_out, int out_size)
{
    const float* obs = (const float*)d_in[0];
    const float* act = (const float*)d_in[1];
    const int*   msk = (const int*)  d_in[2];
    const float* Wk  = (const float*)d_in[3];
    const float* bk  = (const float*)d_in[4];
    const float* Wv  = (const float*)d_in[5];
    const float* bv  = (const float*)d_in[6];
    const float* Wq  = (const float*)d_in[7];
    const float* bq  = (const float*)d_in[8];
    const float* Wks = (const float*)d_in[9];
    const float* bks = (const float*)d_in[10];
    const float* Wvs = (const float*)d_in[11];
    const float* bvs = (const float*)d_in[12];
    const float* Wp  = (const float*)d_in[13];
    const float* bp  = (const float*)d_in[14];
    float* out = (float*)d_out;

    float *pk, *pv, *pq, *psk, *psv, *py;
    cudaGetSymbolAddress((void**)&pk,  g_k);
    cudaGetSymbolAddress((void**)&pv,  g_v);
    cudaGetSymbolAddress((void**)&pq,  g_q);
    cudaGetSymbolAddress((void**)&psk, g_sk);
    cudaGetSymbolAddress((void**)&psv, g_sv);
    cudaGetSymbolAddress((void**)&py,  g_y);

    dim3 gdim(Dc / 64, Mc / 64);   // (4, 128)

    // Projections
    gemm_bias_kernel<<<gdim, 256>>>(obs, act, Dc, 2 * Dc, Wk,  bk,  pk,  Dc);
    gemm_bias_kernel<<<gdim, 256>>>(obs, act, Dc, 2 * Dc, Wv,  bv,  pv,  Dc);
    gemm_bias_kernel<<<gdim, 256>>>(obs, obs, Dc, Dc,     Wq,  bq,  pq,  Dc);
    gemm_bias_kernel<<<gdim, 256>>>(obs, obs, Dc, Dc,     Wks, bks, psk, Dc);
    gemm_bias_kernel<<<gdim, 256>>>(obs, obs, Dc, Dc,     Wvs, bvs, psv, Dc);

    // Attention
    dim3 adim(Lc / 128, Bc * Hc);  // (8, 64)
    attn_kernel<<<adim, 128>>>(pq, pk, pv, psk, psv, msk, py);

    // Output projection
    gemm_bias_kernel<<<gdim, 256>>>(py, py, Dc, Dc, Wp, bp, out, Dc);
}